// round 4
// baseline (speedup 1.0000x reference)
#include <cuda_runtime.h>
#include <cstdint>

// Problem constants
#define NB      16
#define CDIM    64
#define HWDIM   4096          // 64*64
#define NTOT    65536         // NB*HWDIM
#define KCB     512           // n_embeddings
#define OUT_Q   4194304       // NB*CDIM*HWDIM
// out layout (all f32): [quantized OUT_Q][loss][perplexity][active][indices NTOT]
#define OFF_LOSS (OUT_Q)
#define OFF_PERP (OUT_Q + 1)
#define OFF_ACT  (OUT_Q + 2)
#define OFF_IDX  (OUT_Q + 3)

#define SMEM_BYTES (KCB*CDIM*4 + KCB*4 + KCB*4)   // E + hist + norms = 135168

// Accumulators: zero at module load (.bss); vq_finalize re-zeroes them after
// use so every graph replay starts from zero. No init kernel needed.
__device__ float        g_loss;
__device__ unsigned int g_hist[KCB];

// ---- packed f32x2 helpers (FFMA2 path; PTX-only per sm_103a SASS rules) ----
__device__ __forceinline__ uint64_t pack2(float lo, float hi) {
    uint64_t r; asm("mov.b64 %0, {%1, %2};" : "=l"(r) : "f"(lo), "f"(hi)); return r;
}
__device__ __forceinline__ void unpack2(uint64_t v, float& lo, float& hi) {
    asm("mov.b64 {%0, %1}, %2;" : "=f"(lo), "=f"(hi) : "l"(v));
}
__device__ __forceinline__ void fma2(uint64_t& d, uint64_t a, uint64_t b) {
    asm("fma.rn.f32x2 %0, %1, %2, %0;" : "+l"(d) : "l"(a), "l"(b));
}
__device__ __forceinline__ uint64_t add2(uint64_t a, uint64_t b) {
    uint64_t r; asm("add.rn.f32x2 %0, %1, %2;" : "=l"(r) : "l"(a), "l"(b)); return r;
}

// ---------------------------------------------------------------------------
// main: per-point argmin over 512 codes (packed f32x2 math), write quantized
//       output + index, shared histogram + block loss reduction
// ---------------------------------------------------------------------------
extern __shared__ float s_dyn[];

__global__ __launch_bounds__(512, 1)
void vq_main(const float* __restrict__ x,
             const float* __restrict__ E,
             float* __restrict__ out) {
    float*        sE    = s_dyn;                                // KCB*CDIM
    unsigned int* shist = (unsigned int*)(s_dyn + KCB * CDIM);  // KCB
    float*        snorm = (float*)(shist + KCB);                // KCB
    __shared__ float s_warpsum[16];

    const int tid = threadIdx.x;

    // stage codebook into smem (coalesced float4)
    {
        const float4* Eg  = reinterpret_cast<const float4*>(E);
        float4*       sE4 = reinterpret_cast<float4*>(sE);
#pragma unroll
        for (int i = tid; i < KCB * CDIM / 4; i += 512) sE4[i] = Eg[i];
    }
    __syncthreads();

    // per-block codebook row norms (one row/thread; replaces the init kernel)
    {
        const float4* row = reinterpret_cast<const float4*>(sE + tid * CDIM);
        float s = 0.f;
#pragma unroll
        for (int i = 0; i < CDIM / 4; i++) {
            float4 v = row[i];
            s = fmaf(v.x, v.x, s);
            s = fmaf(v.y, v.y, s);
            s = fmaf(v.z, v.z, s);
            s = fmaf(v.w, v.w, s);
        }
        snorm[tid] = s;
        shist[tid] = 0u;
    }
    __syncthreads();

    const int n  = blockIdx.x * 512 + tid;      // one point per thread
    const int b  = n >> 12;
    const int hw = n & (HWDIM - 1);

    // load x row (BCHW: stride HWDIM along channels; coalesced across threads)
    // pack into f32x2 pairs matching codebook smem layout (even ch = low half)
    uint64_t xp2[CDIM / 2];                     // 32 packed pairs
    float xnorm;
    {
        const float* xp = x + (size_t)b * CDIM * HWDIM + hw;
        uint64_t nacc = 0ull;                   // {0.f, 0.f}
#pragma unroll
        for (int i = 0; i < CDIM / 2; i++) {
            float lo = xp[(size_t)(2*i + 0) * HWDIM];
            float hi = xp[(size_t)(2*i + 1) * HWDIM];
            xp2[i] = pack2(lo, hi);
            fma2(nacc, xp2[i], xp2[i]);
        }
        float nl, nh; unpack2(nacc, nl, nh);
        xnorm = nl + nh;
    }

    const uint32_t sbase = (uint32_t)__cvta_generic_to_shared(sE);

    // argmin_k  ||e_k||^2 - 2 x.e_k   (||x||^2 constant per row)
    float bestd = 3.4e38f;
    int   bestk = 0;
#pragma unroll 2
    for (int k = 0; k < KCB; k++) {
        const uint32_t ea = sbase + (uint32_t)k * (CDIM * 4);
        uint64_t a0 = 0ull, a1 = 0ull, a2 = 0ull, a3 = 0ull;
        // FULL row: 16 x 16B = 256B = 64 floats = 32 f32x2 pairs
#pragma unroll
        for (int i = 0; i < 16; i++) {
            uint64_t e0, e1;                    // {e[4i],e[4i+1]},{e[4i+2],e[4i+3]}
            asm("ld.shared.v2.b64 {%0, %1}, [%2];"
                : "=l"(e0), "=l"(e1) : "r"(ea + i * 16));
            if (i & 1) { fma2(a2, xp2[2*i], e0); fma2(a3, xp2[2*i+1], e1); }
            else       { fma2(a0, xp2[2*i], e0); fma2(a1, xp2[2*i+1], e1); }
        }
        uint64_t s01 = add2(a0, a1);
        uint64_t s23 = add2(a2, a3);
        uint64_t s   = add2(s01, s23);
        float dl, dh; unpack2(s, dl, dh);
        float dot  = dl + dh;
        float dist = fmaf(-2.f, dot, snorm[k]);
        if (dist < bestd) { bestd = dist; bestk = k; }   // strict < keeps first
    }

    // commitment-loss contribution: ||x - e_best||^2 = bestd + ||x||^2
    float lossn = bestd + xnorm;

    atomicAdd(&shist[bestk], 1u);

    // write quantized output (gather code row from gmem/L2; coalesced stores)
    {
        const float4* eg = reinterpret_cast<const float4*>(E + bestk * CDIM);
        float*        op = out + (size_t)b * CDIM * HWDIM + hw;
#pragma unroll
        for (int i = 0; i < CDIM / 4; i++) {
            float4 ev = eg[i];
            op[(size_t)(4*i+0) * HWDIM] = ev.x;
            op[(size_t)(4*i+1) * HWDIM] = ev.y;
            op[(size_t)(4*i+2) * HWDIM] = ev.z;
            op[(size_t)(4*i+3) * HWDIM] = ev.w;
        }
    }
    out[OFF_IDX + n] = (float)bestk;

    // block-reduce loss
#pragma unroll
    for (int off = 16; off; off >>= 1)
        lossn += __shfl_xor_sync(0xFFFFFFFFu, lossn, off);
    if ((tid & 31) == 0) s_warpsum[tid >> 5] = lossn;
    __syncthreads();

    if (tid < KCB) atomicAdd(&g_hist[tid], shist[tid]);
    if (tid == 0) {
        float bsum = 0.f;
#pragma unroll
        for (int i = 0; i < 16; i++) bsum += s_warpsum[i];
        atomicAdd(&g_loss, bsum);
    }
}

// ---------------------------------------------------------------------------
// finalize: perplexity + loss + active_codes scalars; then re-zero the
// accumulators so the next graph replay starts clean.
// ---------------------------------------------------------------------------
__global__ void vq_finalize(const float* __restrict__ w, float* __restrict__ out) {
    __shared__ float s_ent[16];
    __shared__ float s_act[16];
    int t = threadIdx.x;                        // 512 threads, one code each

    float p   = (float)g_hist[t] * (1.0f / (float)NTOT);
    float ent = p * logf(p + 1e-10f);
    float act = (w[t] >= 0.01f) ? 1.f : 0.f;

#pragma unroll
    for (int off = 16; off; off >>= 1) {
        ent += __shfl_xor_sync(0xFFFFFFFFu, ent, off);
        act += __shfl_xor_sync(0xFFFFFFFFu, act, off);
    }
    if ((t & 31) == 0) { s_ent[t >> 5] = ent; s_act[t >> 5] = act; }
    __syncthreads();
    if (t == 0) {
        float esum = 0.f, asum = 0.f;
#pragma unroll
        for (int i = 0; i < 16; i++) { esum += s_ent[i]; asum += s_act[i]; }
        out[OFF_LOSS] = g_loss * (1.0f / ((float)NTOT * (float)CDIM));
        out[OFF_PERP] = expf(-esum);
        out[OFF_ACT]  = asum;
    }
    __syncthreads();
    g_hist[t] = 0u;                             // reset for next replay
    if (t == 0) g_loss = 0.f;
}

// ---------------------------------------------------------------------------
extern "C" void kernel_launch(void* const* d_in, const int* in_sizes, int n_in,
                              void* d_out, int out_size) {
    const float* x = (const float*)d_in[0];   // [16,64,64,64]
    const float* E = (const float*)d_in[1];   // [512,64]
    const float* w = (const float*)d_in[2];   // [512]
    float* out = (float*)d_out;

    cudaFuncSetAttribute(vq_main, cudaFuncAttributeMaxDynamicSharedMemorySize,
                         SMEM_BYTES);

    vq_main<<<NTOT / 512, 512, SMEM_BYTES>>>(x, E, out);
    vq_finalize<<<1, 512>>>(w, out);
}